// round 1
// baseline (speedup 1.0000x reference)
#include <cuda_runtime.h>
#include <math.h>

#define TT 4096
#define CC 512
#define BB 32
#define WW 2055          // DWT output length: floor((T + 16 - 1)/2)
#define PITCH 2056
#define NROWS (BB*CC)    // 16384

// db8 filter banks (derived from DB8_DEC_LO):
// DEC_LO = L; DEC_HI[d] = L[15-d]*(-1)^(15-d); REC_LO[j]=L[15-j]; REC_HI[j]=L[j]*(-1)^j
__constant__ float cDLO[16] = {
 -0.00011747678400228192f, 0.0006754494059985568f, -0.0003917403729959771f, -0.00487035299301066f,
  0.008746094047015655f,   0.013981027917015516f,  -0.04408825393106472f,   -0.01736930100202211f,
  0.128747426620186f,      0.00047248457399797254f,-0.2840155429624281f,    -0.015829105256023893f,
  0.5853546836548691f,     0.6756307362980128f,     0.3128715909144659f,     0.05441584224308161f };
__constant__ float cDHI[16] = {
 -0.05441584224308161f,    0.3128715909144659f,    -0.6756307362980128f,     0.5853546836548691f,
  0.015829105256023893f,  -0.2840155429624281f,    -0.00047248457399797254f, 0.128747426620186f,
  0.01736930100202211f,   -0.04408825393106472f,   -0.013981027917015516f,   0.008746094047015655f,
  0.00487035299301066f,   -0.0003917403729959771f, -0.0006754494059985568f, -0.00011747678400228192f };
__constant__ float cRLO[16] = {
  0.05441584224308161f,    0.3128715909144659f,     0.6756307362980128f,     0.5853546836548691f,
 -0.015829105256023893f,  -0.2840155429624281f,     0.00047248457399797254f, 0.128747426620186f,
 -0.01736930100202211f,   -0.04408825393106472f,    0.013981027917015516f,   0.008746094047015655f,
 -0.00487035299301066f,   -0.0003917403729959771f,  0.0006754494059985568f, -0.00011747678400228192f };
__constant__ float cRHI[16] = {
 -0.00011747678400228192f,-0.0006754494059985568f, -0.0003917403729959771f,  0.00487035299301066f,
  0.008746094047015655f,  -0.013981027917015516f,  -0.04408825393106472f,    0.01736930100202211f,
  0.128747426620186f,     -0.00047248457399797254f,-0.2840155429624281f,     0.015829105256023893f,
  0.5853546836548691f,    -0.6756307362980128f,     0.3128715909144659f,    -0.05441584224308161f };

// Scratch (module-load allocated; no runtime alloc)
__device__ float g_lo[(size_t)NROWS * PITCH];
__device__ float g_hi[(size_t)NROWS * PITCH];
__device__ float g_thr[NROWS];

// ---------------------------------------------------------------------------
// Kernel 1: DWT.  low[i] = sum_d xs(2i+1-d)*DEC_LO[d]  (xs = symmetric ext)
// Block: 32 channels x 64 outputs. Lanes over c for loads, over i for stores.
// ---------------------------------------------------------------------------
__global__ __launch_bounds__(256) void k_dwt(const float* __restrict__ x) {
    const int ITILE = 64;
    int i0 = blockIdx.x * ITILE;
    int c0 = blockIdx.y * 32;
    int b  = blockIdx.z;
    __shared__ float shx[32][143];          // [c][m], odd stride -> conflict-free
    int tid = threadIdx.x, lane = tid & 31, wp = tid >> 5;

    // needed ext args p = 2i+1-d, i in [i0,i0+64), d in [0,15]:
    // p in [2*i0-14, 2*i0+127]  -> 142 samples
    for (int m = wp; m < 142; m += 8) {
        int p = 2 * i0 - 14 + m;
        int t = (p < 0) ? (-1 - p) : ((p >= TT) ? (2 * TT - 1 - p) : p);
        shx[lane][m] = x[((size_t)b * TT + t) * CC + c0 + lane];
    }
    __syncthreads();

    #pragma unroll
    for (int r4 = 0; r4 < 4; r4++) {
        int cc = wp * 4 + r4;
        size_t rowoff = (size_t)(b * CC + c0 + cc) * PITCH;
        #pragma unroll
        for (int half = 0; half < 2; half++) {
            int ii = lane + half * 32;
            int i = i0 + ii;
            if (i < WW) {
                float alo = 0.f, ahi = 0.f;
                #pragma unroll
                for (int d = 0; d < 16; d++) {
                    float v = shx[cc][2 * ii + 15 - d];   // m = p - (2*i0-14)
                    alo = fmaf(v, cDLO[d], alo);
                    ahi = fmaf(v, cDHI[d], ahi);
                }
                g_lo[rowoff + i] = alo;
                g_hi[rowoff + i] = ahi;
            }
        }
    }
}

// ---------------------------------------------------------------------------
// Kernel 2: exact per-row quantile via 32-bit radix select on float bits
// (values are squares >= 0, so uint order == float order).
// One block per row; 2055 values held in registers (<=9/thread).
// ---------------------------------------------------------------------------
__global__ __launch_bounds__(256) void k_quant(const float* __restrict__ qp) {
    int row = blockIdx.x;
    const float* h = g_hi + (size_t)row * PITCH;
    unsigned int vals[9];
    int nv = 0;
    int tid = threadIdx.x;
    for (int idx = tid; idx < WW; idx += 256) {
        float v = h[idx];
        vals[nv++] = __float_as_uint(v * v);
    }
    float q = qp[0];
    float pos = q * (float)(WW - 1);
    int k = (int)floorf(pos);
    if (k < 0) k = 0;
    if (k > WW - 2) k = WW - 2;
    float frac = pos - (float)k;

    __shared__ unsigned int hist[256];
    __shared__ unsigned int sc[256];
    __shared__ int s_sel, s_r;

    unsigned int prefix = 0;
    int r = k;
    for (int shift = 24; shift >= 0; shift -= 8) {
        hist[tid] = 0;
        __syncthreads();
        unsigned int maskhi = (shift == 24) ? 0u : (0xFFFFFFFFu << (shift + 8));
        for (int e = 0; e < nv; e++) {
            unsigned int u = vals[e];
            if ((u & maskhi) == prefix) atomicAdd(&hist[(u >> shift) & 255u], 1u);
        }
        __syncthreads();
        unsigned int hv = hist[tid];
        sc[tid] = hv;
        __syncthreads();
        for (int off = 1; off < 256; off <<= 1) {
            unsigned int add = (tid >= off) ? sc[tid - off] : 0u;
            __syncthreads();
            sc[tid] += add;
            __syncthreads();
        }
        unsigned int incl = sc[tid];
        unsigned int below = incl - hv;
        if ((unsigned)r >= below && (unsigned)r < incl) {
            s_sel = tid;
            s_r = r - (int)below;
        }
        __syncthreads();
        prefix |= ((unsigned int)s_sel) << shift;
        r = s_r;
        __syncthreads();
    }
    // prefix = bits of v[k]; count equals + min strictly-greater for v[k+1]
    __shared__ unsigned int s_eq, s_mg;
    if (tid == 0) { s_eq = 0u; s_mg = 0xFFFFFFFFu; }
    __syncthreads();
    unsigned int leq = 0, lmg = 0xFFFFFFFFu;
    for (int e = 0; e < nv; e++) {
        unsigned int u = vals[e];
        if (u == prefix) leq++;
        else if (u > prefix && u < lmg) lmg = u;
    }
    if (leq) atomicAdd(&s_eq, leq);
    atomicMin(&s_mg, lmg);
    __syncthreads();
    if (tid == 0) {
        float vk = __uint_as_float(prefix);
        int lastEqRank = (k - r) + (int)s_eq - 1;   // (k - r) = #elements < v[k]
        float vk1 = (lastEqRank >= k + 1) ? vk : __uint_as_float(s_mg);
        g_thr[row] = vk * (1.0f - frac) + vk1 * frac;
    }
}

// ---------------------------------------------------------------------------
// Kernel 3: mask + IDWT + transpose to [B,T,C].
// rec[o] = sum_{m=0..7} ca[o>>1 + m]*REC_LO[j] + cdm[...]*REC_HI[j],
//          j = (o even ? 14-2m : 15-2m).  p range per 128-tile: [o0/2, o0/2+70].
// ---------------------------------------------------------------------------
__global__ __launch_bounds__(256) void k_idwt(float* __restrict__ out) {
    int o0 = blockIdx.x * 128;
    int c0 = blockIdx.y * 32;
    int b  = blockIdx.z;
    __shared__ float sha[32][73], shd[32][73];   // odd stride
    int tid = threadIdx.x, lane = tid & 31, wp = tid >> 5;
    int p0 = o0 >> 1;

    for (int cc = wp; cc < 32; cc += 8) {
        int row = b * CC + c0 + cc;
        size_t roff = (size_t)row * PITCH;
        float tv = g_thr[row];
        for (int pp = lane; pp < 71; pp += 32) {
            int p = p0 + pp;                     // always in [0, 2054]
            sha[cc][pp] = g_lo[roff + p];
            float cd = g_hi[roff + p];
            shd[cc][pp] = (cd * cd > tv) ? cd : 0.f;
        }
    }
    __syncthreads();

    #pragma unroll
    for (int s = 0; s < 16; s++) {
        int oo = wp * 16 + s;                    // parity(oo) == parity(s)
        int pl = oo >> 1;
        float acc = 0.f;
        if (s & 1) {
            #pragma unroll
            for (int m = 0; m < 8; m++)
                acc = fmaf(sha[lane][pl + m], cRLO[15 - 2 * m],
                      fmaf(shd[lane][pl + m], cRHI[15 - 2 * m], acc));
        } else {
            #pragma unroll
            for (int m = 0; m < 8; m++)
                acc = fmaf(sha[lane][pl + m], cRLO[14 - 2 * m],
                      fmaf(shd[lane][pl + m], cRHI[14 - 2 * m], acc));
        }
        out[((size_t)(b * TT) + o0 + oo) * CC + c0 + lane] = acc;
    }
}

extern "C" void kernel_launch(void* const* d_in, const int* in_sizes, int n_in,
                              void* d_out, int out_size) {
    const float* x  = (const float*)d_in[0];   // [32, 4096, 512] f32
    const float* qp = (const float*)d_in[1];   // [1] f32
    float* out = (float*)d_out;                // [32, 4096, 512] f32

    dim3 g1((WW + 63) / 64, CC / 32, BB);      // 33 x 16 x 32
    k_dwt<<<g1, 256>>>(x);

    k_quant<<<NROWS, 256>>>(qp);               // 16384 rows

    dim3 g3(TT / 128, CC / 32, BB);            // 32 x 16 x 32
    k_idwt<<<g3, 256>>>(out);
}